// round 11
// baseline (speedup 1.0000x reference)
#include <cuda_runtime.h>
#include <cstdint>

#define MAPSZ 38809      // 197*197
#define NP    196        // 14*14 patches
#define HW    784        // 28*28
#define FULLM 0xFFFFFFFFu
#define MAXRUNS 98       // 14 rows * up to 7 runs

// scratch[z][(i*32 + b)*196 + p] = sum over 6 heads (z half) of att[i,b,j,0,1+p]
__device__ float g_scratch[2][12 * 32 * NP];

// ---------------- Kernel 1: wide phase-A reduction (768 blocks) ----------------
__global__ __launch_bounds__(224)
void phaseA_kernel(const float* __restrict__ att)
{
    const int i = blockIdx.x;      // layer 0..11
    const int b = blockIdx.y;      // batch 0..31
    const int z = blockIdx.z;      // head half 0..1
    const int p = threadIdx.x;     // patch 0..195
    if (p >= NP) return;

    const float* base = att + (size_t)(i * 384 + b * 12 + z * 6) * MAPSZ + 1 + p;
    float s0, s1, s2;
    s0 = __ldg(base + (size_t)0 * MAPSZ) + __ldg(base + (size_t)3 * MAPSZ);
    s1 = __ldg(base + (size_t)1 * MAPSZ) + __ldg(base + (size_t)4 * MAPSZ);
    s2 = __ldg(base + (size_t)2 * MAPSZ) + __ldg(base + (size_t)5 * MAPSZ);
    g_scratch[z][(i * 32 + b) * NP + p] = s0 + (s1 + s2);
}

// ---------------- Kernel 2: threshold, run-graph CCL, compaction ----------------
__global__ __launch_bounds__(1024, 1)
void maskgen_kernel(float* __restrict__ out)
{
    __shared__ float    sh_a14[NP];     // 14x14 attention means
    __shared__ float    sh_part[8];     // warp partial sums for threshold
    __shared__ unsigned sh_final[14];   // final 14x14 mask rows
    __shared__ int      rowoff[16];     // run index range per row
    __shared__ unsigned runmask[MAXRUNS];
    __shared__ int      runrow[MAXRUNS];
    __shared__ int      lab[MAXRUNS];
    __shared__ int      cnt[MAXRUNS];
    __shared__ int      sh_total;
    __shared__ int      sh_wsum[32], sh_wpre[32];

    const int b    = blockIdx.x;
    const int tid  = threadIdx.x;
    const int lane = tid & 31;
    const int w    = tid >> 5;

    // ---------- gather partial sums (L2-resident scratch) + per-warp reduce ----------
    float a = 0.f;
    if (tid < NP) {
        float s0 = 0.f, s1 = 0.f, s2 = 0.f, s3 = 0.f;
        #pragma unroll
        for (int i = 0; i < 12; i += 4) {
            s0 += g_scratch[0][((i + 0) * 32 + b) * NP + tid] + g_scratch[1][((i + 0) * 32 + b) * NP + tid];
            s1 += g_scratch[0][((i + 1) * 32 + b) * NP + tid] + g_scratch[1][((i + 1) * 32 + b) * NP + tid];
            s2 += g_scratch[0][((i + 2) * 32 + b) * NP + tid] + g_scratch[1][((i + 2) * 32 + b) * NP + tid];
            s3 += g_scratch[0][((i + 3) * 32 + b) * NP + tid] + g_scratch[1][((i + 3) * 32 + b) * NP + tid];
        }
        a = ((s0 + s1) + (s2 + s3)) / 144.0f;
        sh_a14[tid] = a;
    }
    if (w < 7) {                                 // tids 0..223 cover all 196 values
        float v = a;
        #pragma unroll
        for (int off = 16; off > 0; off >>= 1)
            v += __shfl_down_sync(FULLM, v, off);
        if (lane == 0) sh_part[w] = v;
    }
    __syncthreads();

    // ---------- warp 0 does ALL of the CCL, warp-synchronously ----------
    if (w == 0) {
        // threshold = mean of a14 (== mean of the 28x28 upsample)
        float v = (lane < 7) ? sh_part[lane] : 0.f;
        #pragma unroll
        for (int off = 16; off > 0; off >>= 1)
            v += __shfl_down_sync(FULLM, v, off);
        const float thr = __shfl_sync(FULLM, v, 0) / 196.0f;

        // mask rows (lane = row, 14 bits)
        uint32_t m = 0;
        if (lane < 14) {
            #pragma unroll
            for (int x = 0; x < 14; ++x)
                m |= (sh_a14[lane * 14 + x] > thr) ? (1u << x) : 0u;
        }

        // run extraction: runs per row + exclusive prefix -> rowoff
        // NOTE: lanes >= 14 have rc == 0, so their exclusive prefix already
        // equals the total run count -> rowoff[14]/rowoff[15] need no shuffle.
        int rc = __popc(m & ~(m << 1));
        int pre = rc;
        #pragma unroll
        for (int off = 1; off < 32; off <<= 1) {
            int t = __shfl_up_sync(FULLM, pre, off);
            if (lane >= off) pre += t;
        }
        const int excl = pre - rc;
        if (lane < 16) rowoff[lane] = excl;
        if (lane < 14) {
            uint32_t mm = m;
            int bi = excl;
            while (mm) {
                uint32_t lo  = mm & (0u - mm);
                uint32_t run = mm & ~(mm + lo);   // contiguous run containing lowest bit
                runmask[bi] = run;
                runrow[bi]  = lane;
                lab[bi]     = bi;
                cnt[bi]     = 0;
                ++bi;
                mm &= ~run;
            }
        }
        __syncwarp();
        const int nruns = rowoff[14];

        // min-label Jacobi + pointer jumping over the run adjacency graph
        volatile int* vlab = lab;
        for (int it = 0; it < MAXRUNS; ++it) {
            bool ch = false;
            for (int r = lane; r < nruns; r += 32) {
                const int y = runrow[r];
                const uint32_t mr = runmask[r];
                int vmin = vlab[r];
                if (y > 0) {
                    const int e = rowoff[y];
                    for (int s = rowoff[y - 1]; s < e; ++s)
                        if (runmask[s] & mr) vmin = min(vmin, vlab[s]);
                }
                if (y < 13) {
                    const int e = rowoff[y + 2];
                    for (int s = rowoff[y + 1]; s < e; ++s)
                        if (runmask[s] & mr) vmin = min(vmin, vlab[s]);
                }
                vmin = vlab[vmin];                 // pointer jump
                vmin = vlab[vmin];
                if (vmin < vlab[r]) { vlab[r] = vmin; ch = true; }
            }
            unsigned anych = __ballot_sync(FULLM, ch);
            __syncwarp();
            if (!anych) break;
        }

        // areas per root
        for (int r = lane; r < nruns; r += 32)
            atomicAdd(&cnt[lab[r]], __popc(runmask[r]));
        __syncwarp();

        // best (area, min-cell): max area, tie -> smallest min cell (== argmax semantics).
        // Root = min run index of its component, so its first bit IS the component min cell.
        int bestkey = 0, bestroot = -1;
        for (int r = lane; r < nruns; r += 32) {
            if (cnt[r] > 0) {
                int mc  = runrow[r] * 14 + (__ffs(runmask[r]) - 1);
                int key = (cnt[r] << 8) | (255 - mc);   // unique per component
                if (key > bestkey) { bestkey = key; bestroot = r; }
            }
        }
        const int gkey = __reduce_max_sync(FULLM, bestkey);
        unsigned who = __ballot_sync(FULLM, (bestkey == gkey) && (gkey > 0));
        int groot = -1;
        if (who) groot = __shfl_sync(FULLM, bestroot, __ffs(who) - 1);

        const bool keep = (gkey > 0) && (((gkey >> 8) * 4) >= 160);  // THRESHOLD_POINT @28x28
        if (lane < 14) {
            uint32_t fin = m;
            if (keep) {
                fin = 0;
                const int e = rowoff[lane + 1];
                for (int s = rowoff[lane]; s < e; ++s)
                    if (lab[s] == groot) fin |= runmask[s];
            }
            sh_final[lane] = fin;
        }
    }
    __syncthreads();

    // ---------- final 28x28 mask + stable "fg first, then bg" compaction ----------
    int f = 0;
    if (tid < HW) {
        int y = tid / 28, x = tid - y * 28;
        f = (sh_final[y >> 1] >> (x >> 1)) & 1;
    }
    unsigned bal = __ballot_sync(FULLM, f);
    const int lanepre = __popc(bal & ((1u << lane) - 1));
    if (lane == 0) sh_wsum[w] = __popc(bal);
    __syncthreads();
    if (w == 0) {
        int v = sh_wsum[lane];
        int inc = v;
        #pragma unroll
        for (int off = 1; off < 32; off <<= 1) {
            int t = __shfl_up_sync(FULLM, inc, off);
            if (lane >= off) inc += t;
        }
        sh_wpre[lane] = inc - v;
        if (lane == 31) sh_total = inc;   // total fg count
    }
    __syncthreads();

    if (tid < HW) {
        int fgpre = sh_wpre[w] + lanepre;
        int pos = f ? fgpre : (sh_total + (tid - fgpre));
        out[b * HW + pos] = (float)(tid + 1);   // __output__ is float32
    }
}

extern "C" void kernel_launch(void* const* d_in, const int* in_sizes, int n_in,
                              void* d_out, int out_size)
{
    (void)in_sizes; (void)n_in; (void)out_size;
    const float* att = (const float*)d_in[0];
    float* out = (float*)d_out;

    dim3 gridA(12, 32, 2);
    phaseA_kernel<<<gridA, 224>>>(att);
    maskgen_kernel<<<32, 1024>>>(out);
}

// round 13
// speedup vs baseline: 1.4289x; 1.4289x over previous
#include <cuda_runtime.h>
#include <cstdint>

#define MAPSZ 38809      // 197*197
#define NP    196        // 14*14 patches
#define HW    784        // 28*28
#define FULLM 0xFFFFFFFFu
#define SLOTP 7          // padded run slots per row (max runs in 14 bits = 7)
#define SL    98         // 14 * SLOTP

// scratch[z][(i*32 + b)*196 + p] = sum over 6 heads (z half) of att[i,b,j,0,1+p]
__device__ float g_scratch[2][12 * 32 * NP];

// ---------------- Kernel 1: wide phase-A reduction (768 blocks) ----------------
__global__ __launch_bounds__(224)
void phaseA_kernel(const float* __restrict__ att)
{
    const int i = blockIdx.x;      // layer 0..11
    const int b = blockIdx.y;      // batch 0..31
    const int z = blockIdx.z;      // head half 0..1
    const int p = threadIdx.x;     // patch 0..195
    if (p >= NP) return;

    const float* base = att + (size_t)(i * 384 + b * 12 + z * 6) * MAPSZ + 1 + p;
    float s0, s1, s2;
    s0 = __ldg(base + (size_t)0 * MAPSZ) + __ldg(base + (size_t)3 * MAPSZ);
    s1 = __ldg(base + (size_t)1 * MAPSZ) + __ldg(base + (size_t)4 * MAPSZ);
    s2 = __ldg(base + (size_t)2 * MAPSZ) + __ldg(base + (size_t)5 * MAPSZ);
    g_scratch[z][(i * 32 + b) * NP + p] = s0 + (s1 + s2);
}

// ---------------- Kernel 2: threshold, padded run-graph CCL, compaction ----------------
__global__ __launch_bounds__(1024, 1)
void maskgen_kernel(float* __restrict__ out)
{
    __shared__ float    sh_a14[NP];     // 14x14 attention means
    __shared__ float    sh_part[8];     // warp partial sums for threshold
    __shared__ unsigned sh_data[SL];    // slot: runmask(16) | label<<16
    __shared__ int      sh_cnt[SL];     // per-root areas (14x14 cells)
    __shared__ unsigned sh_final[14];   // final 14x14 mask rows
    __shared__ int      sh_total;
    __shared__ int      sh_wsum[32], sh_wpre[32];

    const int b    = blockIdx.x;
    const int tid  = threadIdx.x;
    const int lane = tid & 31;
    const int w    = tid >> 5;

    // ---------- gather partial sums (L2-resident scratch) + per-warp reduce ----------
    float a = 0.f;
    if (tid < NP) {
        float s0 = 0.f, s1 = 0.f, s2 = 0.f, s3 = 0.f;
        #pragma unroll
        for (int i = 0; i < 12; i += 4) {
            s0 += g_scratch[0][((i + 0) * 32 + b) * NP + tid] + g_scratch[1][((i + 0) * 32 + b) * NP + tid];
            s1 += g_scratch[0][((i + 1) * 32 + b) * NP + tid] + g_scratch[1][((i + 1) * 32 + b) * NP + tid];
            s2 += g_scratch[0][((i + 2) * 32 + b) * NP + tid] + g_scratch[1][((i + 2) * 32 + b) * NP + tid];
            s3 += g_scratch[0][((i + 3) * 32 + b) * NP + tid] + g_scratch[1][((i + 3) * 32 + b) * NP + tid];
        }
        a = ((s0 + s1) + (s2 + s3)) / 144.0f;
        sh_a14[tid] = a;
    }
    if (w < 7) {                                 // tids 0..223 cover all 196 values
        float v = a;
        #pragma unroll
        for (int off = 16; off > 0; off >>= 1)
            v += __shfl_down_sync(FULLM, v, off);
        if (lane == 0) sh_part[w] = v;
    }
    __syncthreads();

    // ---------- warp 0: threshold + CCL, fully warp-synchronous ----------
    if (w == 0) {
        // threshold = mean of a14 (== mean of the 28x28 upsample)
        float v = (lane < 7) ? sh_part[lane] : 0.f;
        #pragma unroll
        for (int off = 16; off > 0; off >>= 1)
            v += __shfl_down_sync(FULLM, v, off);
        const float thr = __shfl_sync(FULLM, v, 0) / 196.0f;

        // mask rows (lane = row, 14 bits)
        uint32_t m = 0;
        if (lane < 14) {
            #pragma unroll
            for (int x = 0; x < 14; ++x)
                m |= (sh_a14[lane * 14 + x] > thr) ? (1u << x) : 0u;
        }

        // run extraction into FIXED 7 slots per row; empty slot: mask=0, label=self
        if (lane < 14) {
            uint32_t mm = m;
            #pragma unroll
            for (int j = 0; j < SLOTP; ++j) {
                uint32_t run = 0;
                if (mm) {
                    uint32_t lo = mm & (0u - mm);
                    run = mm & ~(mm + lo);        // contiguous run containing lowest bit
                    mm &= ~run;
                }
                const int s = lane * SLOTP + j;
                sh_data[s] = run | ((unsigned)s << 16);
                sh_cnt[s]  = 0;
            }
        }
        __syncwarp();

        // per-lane slot constants (up to 4 slots/lane)
        int      rr[4], rlab[4], rup[4], rdn[4], rrow[4];
        uint32_t rmk[4];
        bool     rv[4];
        #pragma unroll
        for (int k = 0; k < 4; ++k) {
            const int r = lane + 32 * k;
            rv[k] = (r < SL);
            rr[k] = rv[k] ? r : 0;
            const int row = rr[k] / SLOTP;
            rrow[k] = row;
            rmk[k]  = rv[k] ? (sh_data[rr[k]] & 0xFFFFu) : 0u;
            rlab[k] = rr[k];
            rup[k]  = (row > 0)  ? (row - 1) * SLOTP : -1;
            rdn[k]  = (row < 13) ? (row + 1) * SLOTP : -1;
        }

        // min-label Jacobi + pointer jumping; fixed-shape neighbor scan, no divergence
        for (int it = 0; it < SL; ++it) {
            bool ch = false;
            #pragma unroll
            for (int k = 0; k < 4; ++k) {
                if (rv[k] && rmk[k]) {
                    int vmin = rlab[k];
                    const uint32_t mr = rmk[k];
                    if (rup[k] >= 0) {
                        #pragma unroll
                        for (int j = 0; j < SLOTP; ++j) {
                            const unsigned d = sh_data[rup[k] + j];
                            if (d & mr) vmin = min(vmin, (int)(d >> 16));
                        }
                    }
                    if (rdn[k] >= 0) {
                        #pragma unroll
                        for (int j = 0; j < SLOTP; ++j) {
                            const unsigned d = sh_data[rdn[k] + j];
                            if (d & mr) vmin = min(vmin, (int)(d >> 16));
                        }
                    }
                    vmin = (int)(sh_data[vmin] >> 16);   // pointer jump
                    vmin = (int)(sh_data[vmin] >> 16);
                    if (vmin < rlab[k]) { rlab[k] = vmin; ch = true; }
                }
            }
            const unsigned any = __ballot_sync(FULLM, ch);
            __syncwarp();
            if (!any) break;
            #pragma unroll
            for (int k = 0; k < 4; ++k)
                if (rv[k]) sh_data[rr[k]] = rmk[k] | ((unsigned)rlab[k] << 16);
            __syncwarp();
        }

        // areas per root
        #pragma unroll
        for (int k = 0; k < 4; ++k)
            if (rv[k] && rmk[k]) atomicAdd(&sh_cnt[rlab[k]], __popc(rmk[k]));
        __syncwarp();

        // best (area, min-cell): max area, tie -> smallest min cell (== argmax semantics).
        // Root = min slot index of its component; slot order (row, j) is lex-monotone
        // with (row, leftmost x), so root's first bit IS the component's min flat cell.
        int bestkey = 0, bestroot = -1;
        #pragma unroll
        for (int k = 0; k < 4; ++k) {
            if (rv[k]) {
                const int c = sh_cnt[rr[k]];
                if (c > 0) {
                    const int mc  = rrow[k] * 14 + (__ffs(rmk[k]) - 1);
                    const int key = (c << 8) | (255 - mc);     // unique per component
                    if (key > bestkey) { bestkey = key; bestroot = rr[k]; }
                }
            }
        }
        const int gkey = __reduce_max_sync(FULLM, bestkey);
        const unsigned who = __ballot_sync(FULLM, (bestkey == gkey) && (gkey > 0));
        int groot = -1;
        if (who) groot = __shfl_sync(FULLM, bestroot, __ffs(who) - 1);

        const bool keep = (gkey > 0) && (((gkey >> 8) * 4) >= 160);  // THRESHOLD_POINT @28x28
        if (lane < 14) {
            uint32_t fin = m;
            if (keep) {
                fin = 0;
                #pragma unroll
                for (int j = 0; j < SLOTP; ++j) {
                    const unsigned d = sh_data[lane * SLOTP + j];
                    if ((d & 0xFFFFu) && ((int)(d >> 16) == groot)) fin |= (d & 0xFFFFu);
                }
            }
            sh_final[lane] = fin;
        }
    }
    __syncthreads();

    // ---------- final 28x28 mask + stable "fg first, then bg" compaction ----------
    int f = 0;
    if (tid < HW) {
        int y = tid / 28, x = tid - y * 28;
        f = (sh_final[y >> 1] >> (x >> 1)) & 1;
    }
    unsigned bal = __ballot_sync(FULLM, f);
    const int lanepre = __popc(bal & ((1u << lane) - 1));
    if (lane == 0) sh_wsum[w] = __popc(bal);
    __syncthreads();
    if (w == 0) {
        int v = sh_wsum[lane];
        int inc = v;
        #pragma unroll
        for (int off = 1; off < 32; off <<= 1) {
            int t = __shfl_up_sync(FULLM, inc, off);
            if (lane >= off) inc += t;
        }
        sh_wpre[lane] = inc - v;
        if (lane == 31) sh_total = inc;   // total fg count
    }
    __syncthreads();

    if (tid < HW) {
        int fgpre = sh_wpre[w] + lanepre;
        int pos = f ? fgpre : (sh_total + (tid - fgpre));
        out[b * HW + pos] = (float)(tid + 1);   // __output__ is float32
    }
}

extern "C" void kernel_launch(void* const* d_in, const int* in_sizes, int n_in,
                              void* d_out, int out_size)
{
    (void)in_sizes; (void)n_in; (void)out_size;
    const float* att = (const float*)d_in[0];
    float* out = (float*)d_out;

    dim3 gridA(12, 32, 2);
    phaseA_kernel<<<gridA, 224>>>(att);
    maskgen_kernel<<<32, 1024>>>(out);
}

// round 14
// speedup vs baseline: 1.4320x; 1.0022x over previous
#include <cuda_runtime.h>
#include <cstdint>

#define MAPSZ 38809      // 197*197
#define NP    196        // 14*14 patches
#define HW    784        // 28*28
#define FULLM 0xFFFFFFFFu
#define SLOTP 7          // padded run slots per row (max runs in 14 bits = 7)
#define SL    98         // 14 * SLOTP

// scratch[z][(i*32 + b)*196 + p] = sum over 6 heads (z half) of att[i,b,j,0,1+p]
__device__ float g_scratch[2][12 * 32 * NP];

// ---------------- Kernel 1: wide phase-A reduction (768 blocks) ----------------
__global__ __launch_bounds__(224)
void phaseA_kernel(const float* __restrict__ att)
{
    const int i = blockIdx.x;      // layer 0..11
    const int b = blockIdx.y;      // batch 0..31
    const int z = blockIdx.z;      // head half 0..1
    const int p = threadIdx.x;     // patch 0..195
    if (p >= NP) return;

    const float* base = att + (size_t)(i * 384 + b * 12 + z * 6) * MAPSZ + 1 + p;
    float s0, s1, s2;
    s0 = __ldg(base + (size_t)0 * MAPSZ) + __ldg(base + (size_t)3 * MAPSZ);
    s1 = __ldg(base + (size_t)1 * MAPSZ) + __ldg(base + (size_t)4 * MAPSZ);
    s2 = __ldg(base + (size_t)2 * MAPSZ) + __ldg(base + (size_t)5 * MAPSZ);
    g_scratch[z][(i * 32 + b) * NP + p] = s0 + (s1 + s2);
}

// ---------------- Kernel 2: threshold, run-graph CCL (precomputed adjacency) ----------------
__global__ __launch_bounds__(1024, 1)
void maskgen_kernel(float* __restrict__ out)
{
    __shared__ float    sh_a14[NP];     // 14x14 attention means
    __shared__ float    sh_part[8];     // warp partial sums for threshold
    __shared__ unsigned sh_data[SL];    // slot: runmask(16) | label<<16
    __shared__ uint4    sh_adj[SL];     // 16 byte-packed neighbor slot ids
    __shared__ int      sh_cnt[SL];     // per-root areas (14x14 cells)
    __shared__ unsigned sh_final[14];   // final 14x14 mask rows
    __shared__ int      sh_total;
    __shared__ int      sh_wsum[32], sh_wpre[32];

    const int b    = blockIdx.x;
    const int tid  = threadIdx.x;
    const int lane = tid & 31;
    const int w    = tid >> 5;

    // ---------- gather partial sums (L2-resident scratch) + per-warp reduce ----------
    float a = 0.f;
    if (tid < NP) {
        float s0 = 0.f, s1 = 0.f, s2 = 0.f, s3 = 0.f;
        #pragma unroll
        for (int i = 0; i < 12; i += 4) {
            s0 += g_scratch[0][((i + 0) * 32 + b) * NP + tid] + g_scratch[1][((i + 0) * 32 + b) * NP + tid];
            s1 += g_scratch[0][((i + 1) * 32 + b) * NP + tid] + g_scratch[1][((i + 1) * 32 + b) * NP + tid];
            s2 += g_scratch[0][((i + 2) * 32 + b) * NP + tid] + g_scratch[1][((i + 2) * 32 + b) * NP + tid];
            s3 += g_scratch[0][((i + 3) * 32 + b) * NP + tid] + g_scratch[1][((i + 3) * 32 + b) * NP + tid];
        }
        a = ((s0 + s1) + (s2 + s3)) / 144.0f;
        sh_a14[tid] = a;
    }
    if (w < 7) {                                 // tids 0..223 cover all 196 values
        float v = a;
        #pragma unroll
        for (int off = 16; off > 0; off >>= 1)
            v += __shfl_down_sync(FULLM, v, off);
        if (lane == 0) sh_part[w] = v;
    }
    __syncthreads();

    // ---------- warp 0: threshold + CCL, fully warp-synchronous ----------
    if (w == 0) {
        // threshold = mean of a14 (== mean of the 28x28 upsample)
        float v = (lane < 7) ? sh_part[lane] : 0.f;
        #pragma unroll
        for (int off = 16; off > 0; off >>= 1)
            v += __shfl_down_sync(FULLM, v, off);
        const float thr = __shfl_sync(FULLM, v, 0) / 196.0f;

        // mask rows (lane = row, 14 bits)
        uint32_t m = 0;
        if (lane < 14) {
            #pragma unroll
            for (int x = 0; x < 14; ++x)
                m |= (sh_a14[lane * 14 + x] > thr) ? (1u << x) : 0u;
        }

        // run extraction into FIXED 7 slots per row; empty slot: mask=0, label=self
        if (lane < 14) {
            uint32_t mm = m;
            #pragma unroll
            for (int j = 0; j < SLOTP; ++j) {
                uint32_t run = 0;
                if (mm) {
                    uint32_t lo = mm & (0u - mm);
                    run = mm & ~(mm + lo);        // contiguous run containing lowest bit
                    mm &= ~run;
                }
                const int s = lane * SLOTP + j;
                sh_data[s] = run | ((unsigned)s << 16);
                sh_cnt[s]  = 0;
            }
        }
        __syncwarp();

        // per-lane slot registers + ONE-TIME adjacency precompute (byte-packed ids)
        int      rr[4], rlab[4];
        uint32_t rmk[4];
        bool     rv[4];
        #pragma unroll
        for (int k = 0; k < 4; ++k) {
            const int r = lane + 32 * k;
            rv[k]   = (r < SL);
            rr[k]   = rv[k] ? r : 0;
            rmk[k]  = rv[k] ? (sh_data[rr[k]] & 0xFFFFu) : 0u;
            rlab[k] = rr[k];
            if (rv[k]) {
                const int row = rr[k] / SLOTP;
                const uint32_t mr = rmk[k];
                // self-replicated padding; insert found neighbors byte-by-byte
                const unsigned long long selfrep = (unsigned long long)rr[k] * 0x0101010101010101ULL;
                unsigned long long plo = selfrep, phi = selfrep;
                int nb = 0;
                if (mr) {
                    #pragma unroll
                    for (int dly = 0; dly < 2; ++dly) {
                        const int nrow = row + (dly ? 1 : -1);
                        if (nrow >= 0 && nrow < 14) {
                            const int base = nrow * SLOTP;
                            #pragma unroll
                            for (int j = 0; j < SLOTP; ++j) {
                                const unsigned d = sh_data[base + j];
                                if (d & mr) {
                                    const unsigned long long id = (unsigned long long)(base + j);
                                    const int sh = (nb & 7) * 8;
                                    if (nb < 8) plo = (plo & ~(0xFFULL << sh)) | (id << sh);
                                    else        phi = (phi & ~(0xFFULL << sh)) | (id << sh);
                                    ++nb;
                                }
                            }
                        }
                    }
                }
                sh_adj[rr[k]] = make_uint4((unsigned)plo, (unsigned)(plo >> 32),
                                           (unsigned)phi, (unsigned)(phi >> 32));
            }
        }
        __syncwarp();

        // min-label Jacobi + pointer jumping; adjacency is one LDS.128 + 16 batched loads
        for (int it = 0; it < SL; ++it) {
            bool ch = false;
            #pragma unroll
            for (int k = 0; k < 4; ++k) {
                if (rv[k] && rmk[k]) {
                    const uint4 aj = sh_adj[rr[k]];
                    int l0  = (int)(sh_data[aj.x         & 0xFF] >> 16);
                    int l1  = (int)(sh_data[(aj.x >>  8) & 0xFF] >> 16);
                    int l2  = (int)(sh_data[(aj.x >> 16) & 0xFF] >> 16);
                    int l3  = (int)(sh_data[(aj.x >> 24)       ] >> 16);
                    int l4  = (int)(sh_data[aj.y         & 0xFF] >> 16);
                    int l5  = (int)(sh_data[(aj.y >>  8) & 0xFF] >> 16);
                    int l6  = (int)(sh_data[(aj.y >> 16) & 0xFF] >> 16);
                    int l7  = (int)(sh_data[(aj.y >> 24)       ] >> 16);
                    int l8  = (int)(sh_data[aj.z         & 0xFF] >> 16);
                    int l9  = (int)(sh_data[(aj.z >>  8) & 0xFF] >> 16);
                    int l10 = (int)(sh_data[(aj.z >> 16) & 0xFF] >> 16);
                    int l11 = (int)(sh_data[(aj.z >> 24)       ] >> 16);
                    int l12 = (int)(sh_data[aj.w         & 0xFF] >> 16);
                    int l13 = (int)(sh_data[(aj.w >>  8) & 0xFF] >> 16);
                    int l14 = (int)(sh_data[(aj.w >> 16) & 0xFF] >> 16);
                    int l15 = (int)(sh_data[(aj.w >> 24)       ] >> 16);
                    int vmin = min(min(min(min(l0, l1), min(l2, l3)),
                                       min(min(l4, l5), min(l6, l7))),
                                   min(min(min(l8, l9), min(l10, l11)),
                                       min(min(l12, l13), min(l14, l15))));
                    vmin = min(vmin, rlab[k]);
                    vmin = (int)(sh_data[vmin] >> 16);   // pointer jump
                    vmin = (int)(sh_data[vmin] >> 16);
                    if (vmin < rlab[k]) { rlab[k] = vmin; ch = true; }
                }
            }
            const unsigned any = __ballot_sync(FULLM, ch);
            __syncwarp();
            if (!any) break;
            #pragma unroll
            for (int k = 0; k < 4; ++k)
                if (rv[k]) sh_data[rr[k]] = rmk[k] | ((unsigned)rlab[k] << 16);
            __syncwarp();
        }

        // areas per root
        #pragma unroll
        for (int k = 0; k < 4; ++k)
            if (rv[k] && rmk[k]) atomicAdd(&sh_cnt[rlab[k]], __popc(rmk[k]));
        __syncwarp();

        // best (area, min-cell): max area, tie -> smallest min cell (== argmax semantics).
        // Root = min slot index of its component; slot order (row, j) is lex-monotone
        // with (row, leftmost x), so root's first bit IS the component's min flat cell.
        int bestkey = 0, bestroot = -1;
        #pragma unroll
        for (int k = 0; k < 4; ++k) {
            if (rv[k]) {
                const int c = sh_cnt[rr[k]];
                if (c > 0) {
                    const int mc  = (rr[k] / SLOTP) * 14 + (__ffs(rmk[k]) - 1);
                    const int key = (c << 8) | (255 - mc);     // unique per component
                    if (key > bestkey) { bestkey = key; bestroot = rr[k]; }
                }
            }
        }
        const int gkey = __reduce_max_sync(FULLM, bestkey);
        const unsigned who = __ballot_sync(FULLM, (bestkey == gkey) && (gkey > 0));
        int groot = -1;
        if (who) groot = __shfl_sync(FULLM, bestroot, __ffs(who) - 1);

        const bool keep = (gkey > 0) && (((gkey >> 8) * 4) >= 160);  // THRESHOLD_POINT @28x28
        if (lane < 14) {
            uint32_t fin = m;
            if (keep) {
                fin = 0;
                #pragma unroll
                for (int j = 0; j < SLOTP; ++j) {
                    const unsigned d = sh_data[lane * SLOTP + j];
                    if ((d & 0xFFFFu) && ((int)(d >> 16) == groot)) fin |= (d & 0xFFFFu);
                }
            }
            sh_final[lane] = fin;
        }
    }
    __syncthreads();

    // ---------- final 28x28 mask + stable "fg first, then bg" compaction ----------
    int f = 0;
    if (tid < HW) {
        int y = tid / 28, x = tid - y * 28;
        f = (sh_final[y >> 1] >> (x >> 1)) & 1;
    }
    unsigned bal = __ballot_sync(FULLM, f);
    const int lanepre = __popc(bal & ((1u << lane) - 1));
    if (lane == 0) sh_wsum[w] = __popc(bal);
    __syncthreads();
    if (w == 0) {
        int v = sh_wsum[lane];
        int inc = v;
        #pragma unroll
        for (int off = 1; off < 32; off <<= 1) {
            int t = __shfl_up_sync(FULLM, inc, off);
            if (lane >= off) inc += t;
        }
        sh_wpre[lane] = inc - v;
        if (lane == 31) sh_total = inc;   // total fg count
    }
    __syncthreads();

    if (tid < HW) {
        int fgpre = sh_wpre[w] + lanepre;
        int pos = f ? fgpre : (sh_total + (tid - fgpre));
        out[b * HW + pos] = (float)(tid + 1);   // __output__ is float32
    }
}

extern "C" void kernel_launch(void* const* d_in, const int* in_sizes, int n_in,
                              void* d_out, int out_size)
{
    (void)in_sizes; (void)n_in; (void)out_size;
    const float* att = (const float*)d_in[0];
    float* out = (float*)d_out;

    dim3 gridA(12, 32, 2);
    phaseA_kernel<<<gridA, 224>>>(att);
    maskgen_kernel<<<32, 1024>>>(out);
}